// round 1
// baseline (speedup 1.0000x reference)
#include <cuda_runtime.h>

#define EPS 1e-5f
#define TT 4   // t-pairs per block

// ---- scratch (device globals: no allocation allowed) ----
__device__ float g_total[64L * 128 * 256 * 25];   // (n,c,t,w)
__device__ float g_AeffT[3 * 25 * 28];            // [s][w][v], v padded to 28
__device__ float g_biasA[128 * 25];               // [c][w]
__device__ float g_sum[128];
__device__ float g_sq[128];
__device__ float g_scale[128];
__device__ float g_shift[128];

// ---------------- prep: Aeff^T, biasA, zero stats ----------------
__global__ void prep_kernel(const float* __restrict__ A,
                            const float* __restrict__ PA,
                            const float* __restrict__ bg) {
    __shared__ float cs[3 * 25];
    int tid = threadIdx.x;
    if (tid < 128) { g_sum[tid] = 0.f; g_sq[tid] = 0.f; }
    for (int idx = tid; idx < 1875; idx += 256) {
        int s = idx / 625, r = idx % 625, v = r / 25, w = r % 25;
        g_AeffT[(s * 25 + w) * 28 + v] = A[idx] + PA[idx];
    }
    __syncthreads();
    if (tid < 75) {
        int s = tid / 25, w = tid % 25;
        float acc = 0.f;
        for (int v = 0; v < 25; ++v) acc += g_AeffT[(s * 25 + w) * 28 + v];
        cs[tid] = acc;
    }
    __syncthreads();
    for (int idx = tid; idx < 3200; idx += 256) {
        int c = idx / 25, w = idx % 25;
        g_biasA[idx] = bg[c] * cs[w] + bg[128 + c] * cs[25 + w] + bg[256 + c] * cs[50 + w];
    }
}

// ---------------- main fused kernel ----------------
// thread = (warp cc = 32-channel chunk, lane w = graph node), data = one t-pair (float2)

template<int CC, int S, int G>
__device__ __forceinline__ void do_g(float2* acc, const float* sxf,
                                     const float* sA, const float* sW, int w) {
    constexpr int O0 = S * 128 + CC * 32;
    constexpr int LO = (O0 > G * 48) ? O0 : G * 48;
    constexpr int HI = ((O0 + 32) < (G + 1) * 48) ? (O0 + 32) : (G + 1) * 48;
    float2 xa[8];
#pragma unroll
    for (int j = 0; j < 8; ++j) xa[j] = make_float2(0.f, 0.f);
    const float* arow = sA + (S * 25 + w) * 28;
    const float* xbase = sxf + (G * 8) * 26 * 2;
#pragma unroll 5
    for (int v = 0; v < 25; ++v) {
        float a = arow[v];
#pragma unroll
        for (int j = 0; j < 8; ++j) {
            float2 xv = *reinterpret_cast<const float2*>(xbase + (j * 26 + v) * 2);
            xa[j].x = fmaf(xv.x, a, xa[j].x);
            xa[j].y = fmaf(xv.y, a, xa[j].y);
        }
    }
#pragma unroll
    for (int o = LO; o < HI; ++o) {
        const float* wr = sW + o * 8;
#pragma unroll
        for (int j = 0; j < 8; ++j) {
            float wv = wr[j];
            acc[o - O0].x = fmaf(xa[j].x, wv, acc[o - O0].x);
            acc[o - O0].y = fmaf(xa[j].y, wv, acc[o - O0].y);
        }
    }
}

template<int CC, int S>
__device__ __forceinline__ void do_s(float2* acc, const float* sxf,
                                     const float* sA, const float* sW, int w) {
    constexpr int O0 = S * 128 + CC * 32;
    constexpr int G_LO = O0 / 48;
    constexpr int G_HI = (O0 + 31) / 48;
    do_g<CC, S, G_LO>(acc, sxf, sA, sW, w);
    if constexpr (G_HI != G_LO) do_g<CC, S, G_HI>(acc, sxf, sA, sW, w);
}

template<int CC>
__device__ __forceinline__ void compute_body(float2* acc, const float* sxf,
                                             const float* sA, const float* sW,
                                             const float* sB, int w) {
#pragma unroll
    for (int c = 0; c < 32; ++c) {
        float b = sB[(CC * 32 + c) * 25 + w];
        acc[c] = make_float2(b, b);
    }
    do_s<CC, 0>(acc, sxf, sA, sW, w);
    do_s<CC, 1>(acc, sxf, sA, sW, w);
    do_s<CC, 2>(acc, sxf, sA, sW, w);
}

__global__ void __launch_bounds__(128)
main_kernel(const float* __restrict__ x, const float* __restrict__ Wg) {
    __shared__ __align__(16) float sxf[64 * 26 * 2];   // x tile: [ci][v][tj]
    __shared__ __align__(16) float sA[3 * 25 * 28];    // Aeff^T
    __shared__ __align__(16) float sW[384 * 8];
    __shared__ __align__(16) float sB[128 * 25];

    int tid = threadIdx.x;
    for (int i = tid; i < 2100; i += 128) sA[i] = g_AeffT[i];
    for (int i = tid; i < 3072; i += 128) sW[i] = Wg[i];
    for (int i = tid; i < 3200; i += 128) sB[i] = g_biasA[i];

    int n = blockIdx.x >> 5;                 // 32 t-blocks per n
    int t0b = (blockIdx.x & 31) * (2 * TT);
    int cc = tid >> 5, w = tid & 31;

    for (int tp = 0; tp < TT; ++tp) {
        int t0 = t0b + 2 * tp;
        __syncthreads();  // protect sxf readers of previous iter (and sA/sW/sB loads on iter 0)
        const float* gx = x + (size_t)(n * 64 * 256 + t0) * 25;
        for (int idx = tid; idx < 3200; idx += 128) {
            int ci = idx / 50, r = idx % 50, tj = r / 25, v = r % 25;
            sxf[(ci * 26 + v) * 2 + tj] = gx[ci * 6400 + tj * 25 + v];
        }
        __syncthreads();

        float2 acc[32];
        if (w < 25) {
            switch (cc) {
                case 0:  compute_body<0>(acc, sxf, sA, sW, sB, w); break;
                case 1:  compute_body<1>(acc, sxf, sA, sW, sB, w); break;
                case 2:  compute_body<2>(acc, sxf, sA, sW, sB, w); break;
                default: compute_body<3>(acc, sxf, sA, sW, sB, w); break;
            }
            float* gt = g_total + ((size_t)(n * 128 + cc * 32) * 256 + t0) * 25 + w;
#pragma unroll
            for (int c = 0; c < 32; ++c) {
                gt[(size_t)c * 6400]      = acc[c].x;
                gt[(size_t)c * 6400 + 25] = acc[c].y;
            }
        } else {
#pragma unroll
            for (int c = 0; c < 32; ++c) acc[c] = make_float2(0.f, 0.f);
        }

        // fused BN statistics: per-channel warp reduction over the 25 w-lanes
#pragma unroll
        for (int c = 0; c < 32; ++c) {
            float s1 = acc[c].x + acc[c].y;
            float s2 = acc[c].x * acc[c].x + acc[c].y * acc[c].y;
#pragma unroll
            for (int off = 16; off > 0; off >>= 1) {
                s1 += __shfl_down_sync(0xffffffffu, s1, off);
                s2 += __shfl_down_sync(0xffffffffu, s2, off);
            }
            if (w == 0) {
                atomicAdd(&g_sum[cc * 32 + c], s1);
                atomicAdd(&g_sq[cc * 32 + c], s2);
            }
        }
    }
}

// ---------------- BN finalize ----------------
__global__ void finalize_kernel(const float* __restrict__ gamma,
                                const float* __restrict__ beta) {
    int c = threadIdx.x;
    if (c < 128) {
        const float inv = 1.0f / 409600.0f;   // N*T*V
        float m = g_sum[c] * inv;
        float var = g_sq[c] * inv - m * m;
        float rstd = rsqrtf(var + EPS);
        float sc = rstd * gamma[c];
        g_scale[c] = sc;
        g_shift[c] = beta[c] - m * sc;
    }
}

// ---------------- normalize: y = total*scale[c] + shift[c] ----------------
__global__ void __launch_bounds__(256) norm_kernel(float* __restrict__ y) {
    size_t i4 = (size_t)blockIdx.x * 256 + threadIdx.x;   // exactly 13107200 float4s
    int c = (int)((i4 / 1600) & 127);                     // 1600 float4 per (n,c)
    float4 t = reinterpret_cast<const float4*>(g_total)[i4];
    float sc = g_scale[c], sh = g_shift[c];
    float4 o;
    o.x = fmaf(t.x, sc, sh);
    o.y = fmaf(t.y, sc, sh);
    o.z = fmaf(t.z, sc, sh);
    o.w = fmaf(t.w, sc, sh);
    reinterpret_cast<float4*>(y)[i4] = o;
}

extern "C" void kernel_launch(void* const* d_in, const int* in_sizes, int n_in,
                              void* d_out, int out_size) {
    (void)in_sizes; (void)n_in; (void)out_size;
    const float* x     = (const float*)d_in[0];
    const float* A     = (const float*)d_in[1];
    const float* PA    = (const float*)d_in[2];
    const float* Wg    = (const float*)d_in[3];
    const float* bg    = (const float*)d_in[4];
    const float* gamma = (const float*)d_in[5];
    const float* beta  = (const float*)d_in[6];

    prep_kernel<<<1, 256>>>(A, PA, bg);
    main_kernel<<<2048, 128>>>(x, Wg);          // 64 n × 32 t-blocks
    finalize_kernel<<<1, 128>>>(gamma, beta);
    norm_kernel<<<51200, 256>>>((float*)d_out); // 13107200 float4
}

// round 2
// speedup vs baseline: 2.0636x; 2.0636x over previous
#include <cuda_runtime.h>

#define EPS 1e-5f
#define TT 4   // t-pairs per block

typedef unsigned long long u64;

__device__ __forceinline__ u64 splat2(float x) {
    u64 r; asm("mov.b64 %0,{%1,%1};" : "=l"(r) : "f"(x)); return r;
}
__device__ __forceinline__ float2 unpack2(u64 v) {
    float lo, hi; asm("mov.b64 {%0,%1},%2;" : "=f"(lo), "=f"(hi) : "l"(v));
    return make_float2(lo, hi);
}
__device__ __forceinline__ void fma2(u64& d, u64 a, u64 b) {
    asm("fma.rn.f32x2 %0,%1,%2,%3;" : "=l"(d) : "l"(a), "l"(b), "l"(d));
}

// ---- scratch (device globals: no allocation allowed) ----
__device__ float g_total[64L * 128 * 256 * 25];   // (n,c,t,w)
__device__ float g_AeffT[3 * 25 * 26];            // [s][w][v], v padded to 26 (pad = 0)
__device__ float g_biasA[128 * 25];               // [c][w]
__device__ float g_sum[128];
__device__ float g_sq[128];
__device__ float g_scale[128];
__device__ float g_shift[128];

// ---------------- prep: Aeff^T (padded), biasA, zero stats ----------------
__global__ void prep_kernel(const float* __restrict__ A,
                            const float* __restrict__ PA,
                            const float* __restrict__ bg) {
    __shared__ float cs[3 * 25];
    int tid = threadIdx.x;
    if (tid < 128) { g_sum[tid] = 0.f; g_sq[tid] = 0.f; }
    for (int idx = tid; idx < 3 * 25 * 26; idx += 256) {
        int s = idx / 650, r = idx % 650, w = r / 26, v = r % 26;
        float val = 0.f;
        if (v < 25) {
            int src = s * 625 + v * 25 + w;
            val = A[src] + PA[src];
        }
        g_AeffT[(s * 25 + w) * 26 + v] = val;
    }
    __syncthreads();
    if (tid < 75) {
        int s = tid / 25, w = tid % 25;
        float acc = 0.f;
        for (int v = 0; v < 25; ++v) acc += g_AeffT[(s * 25 + w) * 26 + v];
        cs[tid] = acc;
    }
    __syncthreads();
    for (int idx = tid; idx < 3200; idx += 256) {
        int c = idx / 25, w = idx % 25;
        g_biasA[idx] = bg[c] * cs[w] + bg[128 + c] * cs[25 + w] + bg[256 + c] * cs[50 + w];
    }
}

// ---------------- main fused kernel ----------------
// 256 threads = 8 warps; warp ww owns 16 output channels [ww*16, ww*16+16);
// lane = graph node w (25 active); each thread carries a t-pair packed f32x2.
// Because 16-channel chunks never straddle a 48-wide conv group, each warp
// computes exactly 3 xA instances (one per subset s), each within one group.
__global__ void __launch_bounds__(256)
main_kernel(const float* __restrict__ x, const float* __restrict__ Wg) {
    __shared__ __align__(16) float sxf[64 * 26 * 2];   // x tile: [ci][v(pad26)][tj]
    __shared__ __align__(16) float sA[3 * 25 * 26];    // Aeff^T padded
    __shared__ __align__(16) float sW[384 * 8];
    __shared__ __align__(16) float sB[128 * 25];

    int tid = threadIdx.x;
    for (int i = tid; i < 3 * 25 * 26; i += 256) sA[i] = g_AeffT[i];
    for (int i = tid; i < 3072; i += 256) sW[i] = Wg[i];
    for (int i = tid; i < 3200; i += 256) sB[i] = g_biasA[i];
    // zero x-tile v=25 pads once (never rewritten by the tile loads)
    if (tid < 128) { int ci = tid >> 1, tj = tid & 1; sxf[(ci * 26 + 25) * 2 + tj] = 0.f; }

    int n = blockIdx.x >> 5;                 // 32 t-blocks per n
    int t0b = (blockIdx.x & 31) * (2 * TT);
    int ww = tid >> 5, w = tid & 31;
    int c0 = ww * 16;

    for (int tp = 0; tp < TT; ++tp) {
        int t0 = t0b + 2 * tp;
        __syncthreads();  // protect sxf readers of previous iter (and table loads on iter 0)
        const float* gx = x + (size_t)(n * 64 * 256 + t0) * 25;
        for (int idx = tid; idx < 3200; idx += 256) {
            int ci = idx / 50, r = idx % 50, tj = r / 25, v = r % 25;
            sxf[(ci * 26 + v) * 2 + tj] = gx[ci * 6400 + tj * 25 + v];
        }
        __syncthreads();

        if (w < 25) {
            u64 acc[16];
#pragma unroll
            for (int c = 0; c < 16; ++c) acc[c] = splat2(sB[(c0 + c) * 25 + w]);

#pragma unroll
            for (int s = 0; s < 3; ++s) {
                int O0 = s * 128 + c0;
                int g = O0 / 48;   // whole 16-chunk lies in one group
                u64 xa[8];
#pragma unroll
                for (int j = 0; j < 8; ++j) xa[j] = 0ULL;
                const float* arow = sA + (s * 25 + w) * 26;
                const float* xb = sxf + g * 8 * 52;
#pragma unroll
                for (int vp = 0; vp < 13; ++vp) {
                    float2 ap = *reinterpret_cast<const float2*>(arow + 2 * vp);
                    u64 a0 = splat2(ap.x), a1 = splat2(ap.y);
#pragma unroll
                    for (int j = 0; j < 8; ++j) {
                        ulonglong2 xv = *reinterpret_cast<const ulonglong2*>(xb + j * 52 + 4 * vp);
                        fma2(xa[j], xv.x, a0);
                        fma2(xa[j], xv.y, a1);
                    }
                }
                const float* wr0 = sW + O0 * 8;
#pragma unroll
                for (int c = 0; c < 16; ++c) {
                    const float4* wrow = reinterpret_cast<const float4*>(wr0 + c * 8);
                    float4 w0 = wrow[0], w1 = wrow[1];
                    fma2(acc[c], xa[0], splat2(w0.x));
                    fma2(acc[c], xa[1], splat2(w0.y));
                    fma2(acc[c], xa[2], splat2(w0.z));
                    fma2(acc[c], xa[3], splat2(w0.w));
                    fma2(acc[c], xa[4], splat2(w1.x));
                    fma2(acc[c], xa[5], splat2(w1.y));
                    fma2(acc[c], xa[6], splat2(w1.z));
                    fma2(acc[c], xa[7], splat2(w1.w));
                }
            }

            float* gt = g_total + ((size_t)(n * 128 + c0) * 256 + t0) * 25 + w;
#pragma unroll
            for (int c = 0; c < 16; ++c) {
                float2 r = unpack2(acc[c]);
                gt[(size_t)c * 6400]      = r.x;
                gt[(size_t)c * 6400 + 25] = r.y;
            }
        }
    }
}

// ---------------- BN statistics (memory-bound pass over g_total) ----------------
__global__ void __launch_bounds__(256) stats_kernel() {
    int c = blockIdx.x >> 3;      // channel
    int slab = blockIdx.x & 7;    // 8 n's per slab
    float s1 = 0.f, s2 = 0.f;
    for (int ni = 0; ni < 8; ++ni) {
        int n = slab * 8 + ni;
        const float4* p = reinterpret_cast<const float4*>(
            g_total + (size_t)(n * 128 + c) * 6400);
        for (int i = threadIdx.x; i < 1600; i += 256) {
            float4 v = p[i];
            s1 += v.x + v.y + v.z + v.w;
            s2 += v.x * v.x + v.y * v.y + v.z * v.z + v.w * v.w;
        }
    }
#pragma unroll
    for (int off = 16; off > 0; off >>= 1) {
        s1 += __shfl_down_sync(0xffffffffu, s1, off);
        s2 += __shfl_down_sync(0xffffffffu, s2, off);
    }
    __shared__ float sh1[8], sh2[8];
    if ((threadIdx.x & 31) == 0) { sh1[threadIdx.x >> 5] = s1; sh2[threadIdx.x >> 5] = s2; }
    __syncthreads();
    if (threadIdx.x < 8) {
        s1 = sh1[threadIdx.x]; s2 = sh2[threadIdx.x];
#pragma unroll
        for (int off = 4; off > 0; off >>= 1) {
            s1 += __shfl_down_sync(0xffu, s1, off);
            s2 += __shfl_down_sync(0xffu, s2, off);
        }
        if (threadIdx.x == 0) { atomicAdd(&g_sum[c], s1); atomicAdd(&g_sq[c], s2); }
    }
}

// ---------------- BN finalize ----------------
__global__ void finalize_kernel(const float* __restrict__ gamma,
                                const float* __restrict__ beta) {
    int c = threadIdx.x;
    if (c < 128) {
        const float inv = 1.0f / 409600.0f;   // N*T*V
        float m = g_sum[c] * inv;
        float var = g_sq[c] * inv - m * m;
        float rstd = rsqrtf(var + EPS);
        float sc = rstd * gamma[c];
        g_scale[c] = sc;
        g_shift[c] = beta[c] - m * sc;
    }
}

// ---------------- normalize: y = total*scale[c] + shift[c] ----------------
__global__ void __launch_bounds__(256) norm_kernel(float* __restrict__ y) {
    size_t i4 = (size_t)blockIdx.x * 256 + threadIdx.x;   // exactly 13107200 float4s
    int c = (int)((i4 / 1600) & 127);                     // 1600 float4 per (n,c)
    float4 t = reinterpret_cast<const float4*>(g_total)[i4];
    float sc = g_scale[c], sh = g_shift[c];
    float4 o;
    o.x = fmaf(t.x, sc, sh);
    o.y = fmaf(t.y, sc, sh);
    o.z = fmaf(t.z, sc, sh);
    o.w = fmaf(t.w, sc, sh);
    reinterpret_cast<float4*>(y)[i4] = o;
}

extern "C" void kernel_launch(void* const* d_in, const int* in_sizes, int n_in,
                              void* d_out, int out_size) {
    (void)in_sizes; (void)n_in; (void)out_size;
    const float* x     = (const float*)d_in[0];
    const float* A     = (const float*)d_in[1];
    const float* PA    = (const float*)d_in[2];
    const float* Wg    = (const float*)d_in[3];
    const float* bg    = (const float*)d_in[4];
    const float* gamma = (const float*)d_in[5];
    const float* beta  = (const float*)d_in[6];

    prep_kernel<<<1, 256>>>(A, PA, bg);
    main_kernel<<<2048, 256>>>(x, Wg);          // 64 n × 32 t-blocks
    stats_kernel<<<1024, 256>>>();              // 128 c × 8 slabs
    finalize_kernel<<<1, 128>>>(gamma, beta);
    norm_kernel<<<51200, 256>>>((float*)d_out); // 13107200 float4
}

// round 3
// speedup vs baseline: 2.2613x; 1.0958x over previous
#include <cuda_runtime.h>

#define EPS 1e-5f

typedef unsigned long long u64;

__device__ __forceinline__ u64 splat2(float x) {
    u64 r; asm("mov.b64 %0,{%1,%1};" : "=l"(r) : "f"(x)); return r;
}
__device__ __forceinline__ void fma2(u64& d, u64 a, u64 b) {
    asm("fma.rn.f32x2 %0,%1,%2,%3;" : "=l"(d) : "l"(a), "l"(b), "l"(d));
}

// ---- scratch (device globals: no allocation allowed) ----
__device__ float g_total[64L * 128 * 256 * 25];   // [n][c][tq=64][w=25][t4=4]
__device__ u64   g_A2[3 * 25 * 25];               // [s][w][v] pre-splatted Aeff
__device__ u64   g_W2[384 * 8];                   // [o][j]  pre-splatted Wg
__device__ float g_biasA[128 * 25];               // [c][w]
__device__ float g_sum[128];
__device__ float g_sq[128];
__device__ float g_scale[128];
__device__ float g_shift[128];

// ================= prep: splatted Aeff^T & Wg, biasA, zero stats =================
__global__ void prep_kernel(const float* __restrict__ A,
                            const float* __restrict__ PA,
                            const float* __restrict__ Wg,
                            const float* __restrict__ bg) {
    __shared__ float cs[75];
    int tid = threadIdx.x;
    if (tid < 128) { g_sum[tid] = 0.f; g_sq[tid] = 0.f; }
    for (int idx = tid; idx < 1875; idx += 256) {
        int s = idx / 625, r = idx % 625, w = r / 25, v = r % 25;
        int src = s * 625 + v * 25 + w;
        g_A2[(s * 25 + w) * 25 + v] = splat2(A[src] + PA[src]);
    }
    for (int idx = tid; idx < 3072; idx += 256) g_W2[idx] = splat2(Wg[idx]);
    __syncthreads();
    if (tid < 75) {
        int s = tid / 25, w = tid % 25;
        float acc = 0.f;
        for (int v = 0; v < 25; ++v)
            acc += __longlong_as_double(0), acc += ((const float2*)&g_A2[(s * 25 + w) * 25 + v])->x;
        cs[tid] = acc;
    }
    __syncthreads();
    for (int idx = tid; idx < 3200; idx += 256) {
        int c = idx / 25, w = idx % 25;
        g_biasA[idx] = bg[c] * cs[w] + bg[128 + c] * cs[25 + w] + bg[256 + c] * cs[50 + w];
    }
}

// ================= main fused kernel =================
// 256 thr = 8 warps, lane = node w (25 active), thread carries 4 t's (2 f32x2).
// Stage 1: 10 distinct (s,group) xA instances, split into 20 j-half units,
//          computed cooperatively and shared via smem.
// Stage 2: warp ww owns 16 output channels; epilogue reads xA + splatted W.
// Dynamic smem layout (floats):
//   sxf  [64ci][25v][4t]          : 0     .. 6400
//   sB   [128c][25w]              : 6400  .. 9600
//   sW2  u64[384o][8j]            : 9600  .. 15744
//   sA2  u64[3s*25w][25v]         : 15744 .. 19494
//   xs   [10inst*8j][25w][4t]     : 19496 .. 27496
#define SMEM_FLOATS 27496
#define SMEM_BYTES (SMEM_FLOATS * 4)

__global__ void __launch_bounds__(256, 2)
main_kernel(const float* __restrict__ x) {
    extern __shared__ float smem[];
    float* sxf = smem;
    float* sB  = smem + 6400;
    u64*   sW2 = (u64*)(smem + 9600);
    u64*   sA2 = (u64*)(smem + 15744);
    float* xs  = smem + 19496;

    int tid = threadIdx.x;
    for (int i = tid; i < 3072; i += 256) sW2[i] = g_W2[i];
    for (int i = tid; i < 1875; i += 256) sA2[i] = g_A2[i];
    for (int i = tid; i < 3200; i += 256) sB[i] = g_biasA[i];

    int n  = blockIdx.x >> 4;
    int tb = blockIdx.x & 15;          // 16 t-blocks/n, 4 quads each
    int ww = tid >> 5, w = tid & 31;
    int c0 = ww * 16;
    const float* gxn = x + (size_t)n * 409600;

    for (int tp = 0; tp < 4; ++tp) {
        int tq = tb * 4 + tp;          // t-quad index, t0 = tq*4
        __syncthreads();               // previous consumers done with sxf/xs
        const float* gx = gxn + tq * 100;
        for (int idx = tid; idx < 6400; idx += 256) {
            int ci = idx / 100, vt = idx % 100;
            int t4 = vt / 25, v = vt % 25;
            sxf[ci * 100 + v * 4 + t4] = gx[ci * 6400 + vt];
        }
        __syncthreads();               // tile ready

        // ---- stage 1: cooperative xA (20 units: inst = u>>1, j-half = u&1) ----
        if (w < 25) {
            int nu = (ww < 4) ? 3 : 2;
            for (int k = 0; k < nu; ++k) {
                int u = ww + k * 8;
                int inst = u >> 1, jb = (u & 1) * 4;
                int s, g;
                if (inst < 3)      { s = 0; g = inst; }
                else if (inst < 7) { s = 1; g = inst - 1; }
                else               { s = 2; g = inst - 2; }
                u64 xa0[4] = {0, 0, 0, 0}, xa1[4] = {0, 0, 0, 0};
                const u64* arow = sA2 + (s * 25 + w) * 25;
                const float* xb = sxf + (g * 8 + jb) * 100;
#pragma unroll 5
                for (int v = 0; v < 25; ++v) {
                    u64 av = arow[v];
#pragma unroll
                    for (int j = 0; j < 4; ++j) {
                        ulonglong2 xv = *(const ulonglong2*)(xb + j * 100 + v * 4);
                        fma2(xa0[j], xv.x, av);
                        fma2(xa1[j], xv.y, av);
                    }
                }
#pragma unroll
                for (int j = 0; j < 4; ++j)
                    *(ulonglong2*)(xs + ((inst * 8 + jb + j) * 25 + w) * 4) =
                        make_ulonglong2(xa0[j], xa1[j]);
            }
        }
        __syncthreads();               // xs ready

        // ---- stage 2: epilogue, 16 channels per warp in two 8-channel halves ----
        if (w < 25) {
#pragma unroll
            for (int h = 0; h < 2; ++h) {
                int cb = c0 + h * 8;
                u64 acc0[8], acc1[8];
#pragma unroll
                for (int c = 0; c < 8; ++c) {
                    u64 b = splat2(sB[(cb + c) * 25 + w]);
                    acc0[c] = b; acc1[c] = b;
                }
#pragma unroll
                for (int s = 0; s < 3; ++s) {
                    int O0 = s * 128 + c0;
                    int g = O0 / 48;
                    int inst = g + s;
                    u64 x0[8], x1[8];
#pragma unroll
                    for (int j = 0; j < 8; ++j) {
                        ulonglong2 xv = *(const ulonglong2*)(xs + ((inst * 8 + j) * 25 + w) * 4);
                        x0[j] = xv.x; x1[j] = xv.y;
                    }
                    const u64* wr = sW2 + (s * 128 + cb) * 8;
#pragma unroll
                    for (int c = 0; c < 8; ++c) {
#pragma unroll
                        for (int j = 0; j < 8; ++j) {
                            u64 ws = wr[c * 8 + j];
                            fma2(acc0[c], x0[j], ws);
                            fma2(acc1[c], x1[j], ws);
                        }
                    }
                }
                float* gt = g_total + ((size_t)(n * 128 + cb) * 64 + tq) * 100 + w * 4;
#pragma unroll
                for (int c = 0; c < 8; ++c)
                    *(ulonglong2*)(gt + (size_t)c * 6400) = make_ulonglong2(acc0[c], acc1[c]);
            }
        }
    }
}

// ================= BN statistics (memory-bound pass over g_total) =================
__global__ void __launch_bounds__(256) stats_kernel() {
    int c = blockIdx.x >> 3;
    int slab = blockIdx.x & 7;
    float s1 = 0.f, s2 = 0.f;
    for (int ni = 0; ni < 8; ++ni) {
        int n = slab * 8 + ni;
        const float4* p = reinterpret_cast<const float4*>(
            g_total + (size_t)(n * 128 + c) * 6400);
        for (int i = threadIdx.x; i < 1600; i += 256) {
            float4 v = p[i];
            s1 += v.x + v.y + v.z + v.w;
            s2 += v.x * v.x + v.y * v.y + v.z * v.z + v.w * v.w;
        }
    }
#pragma unroll
    for (int off = 16; off > 0; off >>= 1) {
        s1 += __shfl_down_sync(0xffffffffu, s1, off);
        s2 += __shfl_down_sync(0xffffffffu, s2, off);
    }
    __shared__ float sh1[8], sh2[8];
    if ((threadIdx.x & 31) == 0) { sh1[threadIdx.x >> 5] = s1; sh2[threadIdx.x >> 5] = s2; }
    __syncthreads();
    if (threadIdx.x < 8) {
        s1 = sh1[threadIdx.x]; s2 = sh2[threadIdx.x];
#pragma unroll
        for (int off = 4; off > 0; off >>= 1) {
            s1 += __shfl_down_sync(0xffu, s1, off);
            s2 += __shfl_down_sync(0xffu, s2, off);
        }
        if (threadIdx.x == 0) { atomicAdd(&g_sum[c], s1); atomicAdd(&g_sq[c], s2); }
    }
}

// ================= BN finalize =================
__global__ void finalize_kernel(const float* __restrict__ gamma,
                                const float* __restrict__ beta) {
    int c = threadIdx.x;
    if (c < 128) {
        const float inv = 1.0f / 409600.0f;
        float m = g_sum[c] * inv;
        float var = g_sq[c] * inv - m * m;
        float rstd = rsqrtf(var + EPS);
        float sc = rstd * gamma[c];
        g_scale[c] = sc;
        g_shift[c] = beta[c] - m * sc;
    }
}

// ================= normalize: y[n,c,t,w] from permuted g_total =================
__global__ void __launch_bounds__(256) norm_kernel(float* __restrict__ y) {
    size_t i4 = (size_t)blockIdx.x * 256 + threadIdx.x;   // 13107200 float4s
    size_t ch = i4 / 1600;                                // n*128 + c
    int c = (int)(ch & 127);
    int r = (int)(i4 - ch * 1600);
    int tq = r / 25, w = r - tq * 25;
    float4 t = reinterpret_cast<const float4*>(g_total)[i4];
    float sc = g_scale[c], sh = g_shift[c];
    float* yb = y + (ch * 64 + tq) * 100 + w;             // = ch*6400 + tq*100 + w
    yb[0]  = fmaf(t.x, sc, sh);
    yb[25] = fmaf(t.y, sc, sh);
    yb[50] = fmaf(t.z, sc, sh);
    yb[75] = fmaf(t.w, sc, sh);
}

extern "C" void kernel_launch(void* const* d_in, const int* in_sizes, int n_in,
                              void* d_out, int out_size) {
    (void)in_sizes; (void)n_in; (void)out_size;
    const float* x     = (const float*)d_in[0];
    const float* A     = (const float*)d_in[1];
    const float* PA    = (const float*)d_in[2];
    const float* Wg    = (const float*)d_in[3];
    const float* bg    = (const float*)d_in[4];
    const float* gamma = (const float*)d_in[5];
    const float* beta  = (const float*)d_in[6];

    cudaFuncSetAttribute(main_kernel, cudaFuncAttributeMaxDynamicSharedMemorySize,
                         SMEM_BYTES);

    prep_kernel<<<1, 256>>>(A, PA, Wg, bg);
    main_kernel<<<1024, 256, SMEM_BYTES>>>(x);   // 64 n × 16 t-blocks × 4 quads
    stats_kernel<<<1024, 256>>>();               // 128 c × 8 slabs
    finalize_kernel<<<1, 128>>>(gamma, beta);
    norm_kernel<<<51200, 256>>>((float*)d_out);  // 13107200 float4
}

// round 4
// speedup vs baseline: 2.3856x; 1.0550x over previous
#include <cuda_runtime.h>

#define EPS 1e-5f

typedef unsigned long long u64;

__device__ __forceinline__ u64 splat2(float x) {
    u64 r; asm("mov.b64 %0,{%1,%1};" : "=l"(r) : "f"(x)); return r;
}
__device__ __forceinline__ void fma2(u64& d, u64 a, u64 b) {
    asm("fma.rn.f32x2 %0,%1,%2,%3;" : "=l"(d) : "l"(a), "l"(b), "l"(d));
}

// ---- scratch (device globals: no allocation allowed) ----
__device__ float g_total[64L * 128 * 256 * 25];   // [n][c][tq=64][w=25][t4=4]
__device__ u64   g_A2[3 * 25 * 25];               // [s][w][v] pre-splatted Aeff
__device__ u64   g_W2[384 * 8];                   // [o][j]  pre-splatted Wg
__device__ float g_biasA[128 * 25];               // [c][w]
__device__ float g_sum[128];
__device__ float g_sq[128];
__device__ float g_scale[128];
__device__ float g_shift[128];

// ================= prep: splatted Aeff^T & Wg, biasA, zero stats =================
__global__ void prep_kernel(const float* __restrict__ A,
                            const float* __restrict__ PA,
                            const float* __restrict__ Wg,
                            const float* __restrict__ bg) {
    __shared__ float cs[75];
    int tid = threadIdx.x;
    if (tid < 128) { g_sum[tid] = 0.f; g_sq[tid] = 0.f; }
    for (int idx = tid; idx < 1875; idx += 256) {
        int s = idx / 625, r = idx % 625, w = r / 25, v = r % 25;
        int src = s * 625 + v * 25 + w;
        g_A2[(s * 25 + w) * 25 + v] = splat2(A[src] + PA[src]);
    }
    for (int idx = tid; idx < 3072; idx += 256) g_W2[idx] = splat2(Wg[idx]);
    __syncthreads();
    if (tid < 75) {
        int s = tid / 25, w = tid % 25;
        float acc = 0.f;
        for (int v = 0; v < 25; ++v)
            acc += reinterpret_cast<const float2*>(&g_A2[(s * 25 + w) * 25 + v])->x;
        cs[tid] = acc;
    }
    __syncthreads();
    for (int idx = tid; idx < 3200; idx += 256) {
        int c = idx / 25, w = idx % 25;
        g_biasA[idx] = bg[c] * cs[w] + bg[128 + c] * cs[25 + w] + bg[256 + c] * cs[50 + w];
    }
}

// ---- dummy kernels: shift main_kernel into the ncu-profiled launch slot (#4) ----
__global__ void dummyA_kernel() {}
__global__ void dummyB_kernel() {}

// ================= main fused kernel =================
// 256 thr = 8 warps, lane = node w (25 active), thread carries 4 t's (2 f32x2).
// Stage 1: 10 distinct (s,group) xA instances split into 40 units (2 j's each);
//          exactly 5 units per warp -> no barrier skew. Shared via smem.
// Stage 2: warp ww owns 16 output channels; epilogue reads xA + splatted W.
// Dynamic smem layout (floats):
//   sxf  [64ci][25v][4t]          : 0     .. 6400
//   sW2  u64[384o][8j]            : 6400  .. 12544
//   sA2  u64[3s*25w][25v]         : 12544 .. 16294
//   xs   [10inst*8j][25w][4t]     : 16296 .. 24296   (16B aligned)
#define SMEM_FLOATS 24296
#define SMEM_BYTES (SMEM_FLOATS * 4)

__global__ void __launch_bounds__(256, 2)
main_kernel(const float* __restrict__ x) {
    extern __shared__ float smem[];
    float* sxf = smem;
    u64*   sW2 = (u64*)(smem + 6400);
    u64*   sA2 = (u64*)(smem + 12544);
    float* xs  = smem + 16296;

    int tid = threadIdx.x;
    for (int i = tid; i < 3072; i += 256) sW2[i] = g_W2[i];
    for (int i = tid; i < 1875; i += 256) sA2[i] = g_A2[i];

    int n  = blockIdx.x >> 5;
    int tb = blockIdx.x & 31;          // 32 t-blocks/n, 2 quads each
    int ww = tid >> 5, w = tid & 31;
    int c0 = ww * 16;
    const float* gxn = x + (size_t)n * 409600;

    for (int tp = 0; tp < 2; ++tp) {
        int tq = tb * 2 + tp;          // t-quad index, t0 = tq*4
        __syncthreads();               // previous consumers done with sxf/xs
        const float* gx = gxn + tq * 100;
        for (int idx = tid; idx < 6400; idx += 256) {
            int ci = idx / 100, vt = idx % 100;
            int t4 = vt / 25, v = vt % 25;
            sxf[ci * 100 + v * 4 + t4] = gx[ci * 6400 + vt];
        }
        __syncthreads();               // tile ready

        // ---- stage 1: 40 units (inst = u>>2, j-pair = u&3), 5 per warp ----
        if (w < 25) {
#pragma unroll
            for (int k = 0; k < 5; ++k) {
                int u = ww + k * 8;
                int inst = u >> 2, jb = (u & 3) * 2;
                int s, g;
                if (inst < 3)      { s = 0; g = inst; }
                else if (inst < 7) { s = 1; g = inst - 1; }
                else               { s = 2; g = inst - 2; }
                u64 xa0[2] = {0, 0}, xa1[2] = {0, 0};
                const u64* arow = sA2 + (s * 25 + w) * 25;
                const float* xb = sxf + (g * 8 + jb) * 100;
#pragma unroll 5
                for (int v = 0; v < 25; ++v) {
                    u64 av = arow[v];
#pragma unroll
                    for (int j = 0; j < 2; ++j) {
                        ulonglong2 xv = *(const ulonglong2*)(xb + j * 100 + v * 4);
                        fma2(xa0[j], xv.x, av);
                        fma2(xa1[j], xv.y, av);
                    }
                }
#pragma unroll
                for (int j = 0; j < 2; ++j)
                    *(ulonglong2*)(xs + ((inst * 8 + jb + j) * 25 + w) * 4) =
                        make_ulonglong2(xa0[j], xa1[j]);
            }
        }
        __syncthreads();               // xs ready

        // ---- stage 2: epilogue, 16 channels per warp in two 8-channel halves ----
        if (w < 25) {
#pragma unroll
            for (int h = 0; h < 2; ++h) {
                int cb = c0 + h * 8;
                u64 acc0[8], acc1[8];
#pragma unroll
                for (int c = 0; c < 8; ++c) { acc0[c] = 0ULL; acc1[c] = 0ULL; }
#pragma unroll
                for (int s = 0; s < 3; ++s) {
                    int O0 = s * 128 + c0;
                    int g = O0 / 48;
                    int inst = g + s;
                    u64 x0[8], x1[8];
#pragma unroll
                    for (int j = 0; j < 8; ++j) {
                        ulonglong2 xv = *(const ulonglong2*)(xs + ((inst * 8 + j) * 25 + w) * 4);
                        x0[j] = xv.x; x1[j] = xv.y;
                    }
                    const u64* wr = sW2 + (s * 128 + cb) * 8;
#pragma unroll
                    for (int c = 0; c < 8; ++c) {
#pragma unroll
                        for (int j = 0; j < 8; ++j) {
                            u64 ws = wr[c * 8 + j];
                            fma2(acc0[c], x0[j], ws);
                            fma2(acc1[c], x1[j], ws);
                        }
                    }
                }
                float* gt = g_total + ((size_t)(n * 128 + cb) * 64 + tq) * 100 + w * 4;
#pragma unroll
                for (int c = 0; c < 8; ++c)
                    *(ulonglong2*)(gt + (size_t)c * 6400) = make_ulonglong2(acc0[c], acc1[c]);
            }
        }
    }
}

// ================= BN statistics (bias folded in here) =================
__global__ void __launch_bounds__(256) stats_kernel() {
    int c = blockIdx.x >> 3;
    int slab = blockIdx.x & 7;
    __shared__ float sbias[25];
    if (threadIdx.x < 25) sbias[threadIdx.x] = g_biasA[c * 25 + threadIdx.x];
    __syncthreads();
    float s1 = 0.f, s2 = 0.f;
    for (int ni = 0; ni < 8; ++ni) {
        int n = slab * 8 + ni;
        const float4* p = reinterpret_cast<const float4*>(
            g_total + (size_t)(n * 128 + c) * 6400);
        for (int i = threadIdx.x; i < 1600; i += 256) {
            float4 v = p[i];                 // one float4 == one (tq,w)'s 4 t's
            float b = sbias[i % 25];
            float ax = v.x + b, ay = v.y + b, az = v.z + b, aw = v.w + b;
            s1 += ax + ay + az + aw;
            s2 += ax * ax + ay * ay + az * az + aw * aw;
        }
    }
#pragma unroll
    for (int off = 16; off > 0; off >>= 1) {
        s1 += __shfl_down_sync(0xffffffffu, s1, off);
        s2 += __shfl_down_sync(0xffffffffu, s2, off);
    }
    __shared__ float sh1[8], sh2[8];
    if ((threadIdx.x & 31) == 0) { sh1[threadIdx.x >> 5] = s1; sh2[threadIdx.x >> 5] = s2; }
    __syncthreads();
    if (threadIdx.x < 8) {
        s1 = sh1[threadIdx.x]; s2 = sh2[threadIdx.x];
#pragma unroll
        for (int off = 4; off > 0; off >>= 1) {
            s1 += __shfl_down_sync(0xffu, s1, off);
            s2 += __shfl_down_sync(0xffu, s2, off);
        }
        if (threadIdx.x == 0) { atomicAdd(&g_sum[c], s1); atomicAdd(&g_sq[c], s2); }
    }
}

// ================= BN finalize =================
__global__ void finalize_kernel(const float* __restrict__ gamma,
                                const float* __restrict__ beta) {
    int c = threadIdx.x;
    if (c < 128) {
        const float inv = 1.0f / 409600.0f;
        float m = g_sum[c] * inv;
        float var = g_sq[c] * inv - m * m;
        float rstd = rsqrtf(var + EPS);
        float sc = rstd * gamma[c];
        g_scale[c] = sc;
        g_shift[c] = beta[c] - m * sc;
    }
}

// ================= normalize: y = (total+bias)*scale[c] + shift[c] =================
__global__ void __launch_bounds__(256) norm_kernel(float* __restrict__ y) {
    size_t i4 = (size_t)blockIdx.x * 256 + threadIdx.x;   // 13107200 float4s
    size_t ch = i4 / 1600;                                // n*128 + c
    int c = (int)(ch & 127);
    int r = (int)(i4 - ch * 1600);
    int tq = r / 25, w = r - tq * 25;
    float4 t = reinterpret_cast<const float4*>(g_total)[i4];
    float b = g_biasA[c * 25 + w];
    float sc = g_scale[c], sh = g_shift[c];
    sh = fmaf(b, sc, sh);                                 // fold bias into shift
    float* yb = y + (ch * 64 + tq) * 100 + w;
    yb[0]  = fmaf(t.x, sc, sh);
    yb[25] = fmaf(t.y, sc, sh);
    yb[50] = fmaf(t.z, sc, sh);
    yb[75] = fmaf(t.w, sc, sh);
}

extern "C" void kernel_launch(void* const* d_in, const int* in_sizes, int n_in,
                              void* d_out, int out_size) {
    (void)in_sizes; (void)n_in; (void)out_size;
    const float* x     = (const float*)d_in[0];
    const float* A     = (const float*)d_in[1];
    const float* PA    = (const float*)d_in[2];
    const float* Wg    = (const float*)d_in[3];
    const float* bg    = (const float*)d_in[4];
    const float* gamma = (const float*)d_in[5];
    const float* beta  = (const float*)d_in[6];

    cudaFuncSetAttribute(main_kernel, cudaFuncAttributeMaxDynamicSharedMemorySize,
                         SMEM_BYTES);

    prep_kernel<<<1, 256>>>(A, PA, Wg, bg);     // launch 1
    dummyA_kernel<<<1, 32>>>();                 // launch 2
    dummyB_kernel<<<1, 32>>>();                 // launch 3
    main_kernel<<<2048, 256, SMEM_BYTES>>>(x);  // launch 4  <- profiled slot
    stats_kernel<<<1024, 256>>>();              // launch 5
    finalize_kernel<<<1, 128>>>(gamma, beta);   // launch 6
    norm_kernel<<<51200, 256>>>((float*)d_out); // launch 7
}